// round 11
// baseline (speedup 1.0000x reference)
#include <cuda_runtime.h>

#define BB 64
#define SS 256
#define TT 8
#define DD 256
#define E_EDGES 500000
#define M_CNT 2048
#define ROW_STRIDE (TT * DD)   // 2048 floats between consecutive (b,s) type rows
#define NEG_INF_F (-10000000000.0f)

#define S_TILE 32
#define N_TILES (SS / S_TILE)             // 8
#define LM_BLOCKS (BB * N_TILES)          // 512
#define LEMMA_BLOCKS 2048
#define TOTAL_BLOCKS (LEMMA_BLOCKS + LM_BLOCKS)
#define BATCH_CAP 128                     // max m's per batch (mean 32)
#define N_QUADS (E_EDGES / 4)             // 125000

// Folded linear head: v = w1 @ w2 (D floats), c = b1.w2 + b2
__device__ float g_v[DD];
__device__ float g_c;
// Per-batch m lists (rebuilt every launch)
__device__ int g_cnt[BB];
__device__ int g_list[BB * BATCH_CAP];

// ---------------------------------------------------------------------------
// Prep: blocks 0..7 fold the linear layers; block 8 buckets m's by batch.
// ---------------------------------------------------------------------------
__global__ void prep_kernel(const float* __restrict__ w1,   // [D, D/2]
                            const float* __restrict__ b1,   // [D/2]
                            const float* __restrict__ w2,   // [D/2, 1]
                            const float* __restrict__ b2,   // [1]
                            const int*   __restrict__ bptr) // [M]
{
    const int t    = threadIdx.x;        // 256 threads
    const int lane = t & 31;
    const int warp = t >> 5;             // 0..7

    if (blockIdx.x < 8) {
        const int d0 = blockIdx.x * 32 + warp * 4;
        #pragma unroll
        for (int j = 0; j < 4; j++) {
            const int d = d0 + j;
            const float* row = w1 + (size_t)d * (DD / 2);
            float acc = 0.f;
            #pragma unroll
            for (int k = lane; k < DD / 2; k += 32)
                acc = fmaf(row[k], w2[k], acc);
            #pragma unroll
            for (int off = 16; off > 0; off >>= 1)
                acc += __shfl_xor_sync(0xFFFFFFFFu, acc, off);
            if (lane == 0) g_v[d] = acc;
        }
        if (blockIdx.x == 0 && warp == 0) {
            float c = 0.f;
            #pragma unroll
            for (int k = lane; k < DD / 2; k += 32)
                c = fmaf(b1[k], w2[k], c);
            #pragma unroll
            for (int off = 16; off > 0; off >>= 1)
                c += __shfl_xor_sync(0xFFFFFFFFu, c, off);
            if (lane == 0) g_c = c + b2[0];
        }
    } else {
        if (t < BB) g_cnt[t] = 0;
        __syncthreads();
        for (int m = t; m < M_CNT; m += blockDim.x) {
            int b = bptr[m];
            int slot = atomicAdd(&g_cnt[b], 1);
            if (slot < BATCH_CAP) g_list[b * BATCH_CAP + slot] = m;
        }
    }
}

__device__ __forceinline__ float warp_reduce_sum(float v) {
    #pragma unroll
    for (int off = 16; off > 0; off >>= 1)
        v += __shfl_xor_sync(0xFFFFFFFFu, v, off);
    return v;
}

// ---------------------------------------------------------------------------
// Lemma phase: 8 lanes per edge, 4 edges per warp. Per-lane register
// accumulation over 8 chunks of D; one 3-shfl reduction serves all 4 edges.
// Next quad's indices are prefetched to hide the index->gather serial chain.
// ---------------------------------------------------------------------------
__device__ __forceinline__ void lemma_phase(
    const float* __restrict__ tok, const int* __restrict__ eidx,
    const float* __restrict__ s_v, float* __restrict__ out, int block)
{
    const int lane = threadIdx.x & 31;
    const int sub  = lane >> 3;          // which edge of the quad (0..3)
    const int kl   = lane & 7;           // lane within edge (0..7)
    const int warp   = (block * blockDim.x + threadIdx.x) >> 5;
    const int nwarps = (LEMMA_BLOCKS * blockDim.x) >> 5;

    const float4* vv = reinterpret_cast<const float4*>(s_v);
    const float4* tk = reinterpret_cast<const float4*>(tok);
    const float c = g_c;

    int q = warp;
    if (q >= N_QUADS) return;

    // Prime the pipeline: load this quad's indices.
    int e    = q * 4 + sub;
    int sidx = eidx[e];
    int gidx = eidx[E_EDGES + e];

    while (true) {
        const int qn = q + nwarps;
        // Prefetch next quad's indices (independent of current compute).
        int sidx_n = 0, gidx_n = 0, en = 0;
        const bool more = (qn < N_QUADS);
        if (more) {
            en     = qn * 4 + sub;
            sidx_n = eidx[en];
            gidx_n = eidx[E_EDGES + en];
        }

        const float4* rs = tk + (size_t)sidx * (ROW_STRIDE / 4);
        const float4* rg = tk + (size_t)gidx * (ROW_STRIDE / 4);

        float acc = 0.f;
        #pragma unroll 4
        for (int ch = 0; ch < 8; ch++) {
            const float4 sv = rs[ch * 8 + kl];
            const float4 gv = rg[ch * 8 + kl];
            const float4 w  = vv[ch * 8 + kl];
            acc = fmaf(sv.x * gv.x, w.x, acc);
            acc = fmaf(sv.y * gv.y, w.y, acc);
            acc = fmaf(sv.z * gv.z, w.z, acc);
            acc = fmaf(sv.w * gv.w, w.w, acc);
        }

        // Reduce within each 8-lane group (serves all 4 edges at once).
        acc += __shfl_xor_sync(0xFFFFFFFFu, acc, 4);
        acc += __shfl_xor_sync(0xFFFFFFFFu, acc, 2);
        acc += __shfl_xor_sync(0xFFFFFFFFu, acc, 1);
        if (kl == 0) out[e] = acc + c;   // 4 lanes store 16 contiguous bytes

        if (!more) break;
        q = qn; e = en; sidx = sidx_n; gidx = gidx_n;
    }
}

// ---------------------------------------------------------------------------
// lm phase: block per (batch, s-tile of 32); loop over the batch's m's.
// The 32KB candidate tile is L1-resident after the first m.
// ---------------------------------------------------------------------------
__device__ __forceinline__ void lm_phase(
    const float* __restrict__ tok, const int* __restrict__ lm_idx,
    const int* __restrict__ tpm, float* __restrict__ out,
    float* __restrict__ q, int blk)
{
    const int b    = blk / N_TILES;
    const int tile = blk % N_TILES;
    const int s0   = tile * S_TILE;

    const int t    = threadIdx.x;
    const int lane = t & 31;
    const int warp = t >> 5;             // 0..7

    const int cnt = min(g_cnt[b], BATCH_CAP);
    const int* list = g_list + b * BATCH_CAP;

    const float* base = tok + ((size_t)b * SS + s0) * ROW_STRIDE;
    const int* mrow = tpm + (size_t)b * SS + s0;

    for (int it = 0; it < cnt; it++) {
        const int m = list[it];
        __syncthreads();
        q[t] = tok[(size_t)lm_idx[m] * DD + t];
        __syncthreads();

        const float4* qv = reinterpret_cast<const float4*>(q);
        const float4 q0 = qv[lane];
        const float4 q1 = qv[32 + lane];

        float* orow = out + (size_t)E_EDGES + (size_t)m * SS + s0;

        #pragma unroll
        for (int si = warp; si < S_TILE; si += 8) {
            const float4* cr = reinterpret_cast<const float4*>(base + (size_t)si * ROW_STRIDE);
            const float4 c0 = cr[lane];
            const float4 c1 = cr[32 + lane];

            float acc = 0.f;
            acc = fmaf(q0.x, c0.x, acc);
            acc = fmaf(q0.y, c0.y, acc);
            acc = fmaf(q0.z, c0.z, acc);
            acc = fmaf(q0.w, c0.w, acc);
            acc = fmaf(q1.x, c1.x, acc);
            acc = fmaf(q1.y, c1.y, acc);
            acc = fmaf(q1.z, c1.z, acc);
            acc = fmaf(q1.w, c1.w, acc);

            acc = warp_reduce_sum(acc);
            if (lane == 0)
                orow[si] = (mrow[si] != 0) ? acc : NEG_INF_F;
        }
    }
}

// ---------------------------------------------------------------------------
__global__ __launch_bounds__(256)
void fused_kernel(const float* __restrict__ tok,
                  const int*   __restrict__ eidx,
                  const int*   __restrict__ lm_idx,
                  const int*   __restrict__ tpm,
                  float*       __restrict__ out)
{
    __shared__ float s_buf[DD];          // lemma: v staging; lm: query row
    const int blk = blockIdx.x;
    if (blk < LEMMA_BLOCKS) {
        s_buf[threadIdx.x] = g_v[threadIdx.x];
        __syncthreads();
        lemma_phase(tok, eidx, s_buf, out, blk);
    } else {
        lm_phase(tok, lm_idx, tpm, out, s_buf, blk - LEMMA_BLOCKS);
    }
}

// ---------------------------------------------------------------------------
// Inputs (metadata order):
//  0 token_reprs f32 [B,S,T,D]
//  1 w1 f32 [D,D/2]  2 b1 f32 [D/2]  3 w2 f32 [D/2,1]  4 b2 f32 [1]
//  5 edge_index i32 [2,E]  6 lm_indices i32 [M]  7 batch_pointers i32 [M]
//  8 tree_padding_mask (bool -> int32) [B,S]
// Output: float32, E lemmas followed by M*S lm_preds.
// ---------------------------------------------------------------------------
extern "C" void kernel_launch(void* const* d_in, const int* in_sizes, int n_in,
                              void* d_out, int out_size) {
    const float* tok  = (const float*)d_in[0];
    const float* w1   = (const float*)d_in[1];
    const float* b1   = (const float*)d_in[2];
    const float* w2   = (const float*)d_in[3];
    const float* b2   = (const float*)d_in[4];
    const int*   eidx = (const int*)d_in[5];
    const int*   lmi  = (const int*)d_in[6];
    const int*   bpt  = (const int*)d_in[7];
    const int*   tpm  = (const int*)d_in[8];
    float* out = (float*)d_out;

    prep_kernel<<<9, 256>>>(w1, b1, w2, b2, bpt);
    fused_kernel<<<TOTAL_BLOCKS, 256>>>(tok, eidx, lmi, tpm, out);
}

// round 12
// speedup vs baseline: 1.0082x; 1.0082x over previous
#include <cuda_runtime.h>

#define BB 64
#define SS 256
#define TT 8
#define DD 256
#define E_EDGES 500000
#define M_CNT 2048
#define ROW_STRIDE (TT * DD)   // 2048 floats between consecutive (b,s) type rows
#define NEG_INF_F (-10000000000.0f)

#define S_TILE 32
#define N_TILES (SS / S_TILE)             // 8
#define LM_BLOCKS (BB * N_TILES)          // 512
#define LEMMA_BLOCKS 2048
#define TOTAL_BLOCKS (LEMMA_BLOCKS + LM_BLOCKS)
#define BATCH_CAP 128                     // max m's per batch (mean 32)
#define N_QUADS (E_EDGES / 4)             // 125000

// Folded linear head: v = w1 @ w2 (D floats), c = b1.w2 + b2
__device__ float g_v[DD];
__device__ float g_c;
// Per-batch m lists (rebuilt every launch)
__device__ int g_cnt[BB];
__device__ int g_list[BB * BATCH_CAP];

// ---------------------------------------------------------------------------
// Prep: blocks 0..7 fold the linear layers; block 8 buckets m's by batch.
// ---------------------------------------------------------------------------
__global__ void prep_kernel(const float* __restrict__ w1,   // [D, D/2]
                            const float* __restrict__ b1,   // [D/2]
                            const float* __restrict__ w2,   // [D/2, 1]
                            const float* __restrict__ b2,   // [1]
                            const int*   __restrict__ bptr) // [M]
{
    const int t    = threadIdx.x;        // 256 threads
    const int lane = t & 31;
    const int warp = t >> 5;             // 0..7

    if (blockIdx.x < 8) {
        const int d0 = blockIdx.x * 32 + warp * 4;
        #pragma unroll
        for (int j = 0; j < 4; j++) {
            const int d = d0 + j;
            const float* row = w1 + (size_t)d * (DD / 2);
            float acc = 0.f;
            #pragma unroll
            for (int k = lane; k < DD / 2; k += 32)
                acc = fmaf(row[k], w2[k], acc);
            #pragma unroll
            for (int off = 16; off > 0; off >>= 1)
                acc += __shfl_xor_sync(0xFFFFFFFFu, acc, off);
            if (lane == 0) g_v[d] = acc;
        }
        if (blockIdx.x == 0 && warp == 0) {
            float c = 0.f;
            #pragma unroll
            for (int k = lane; k < DD / 2; k += 32)
                c = fmaf(b1[k], w2[k], c);
            #pragma unroll
            for (int off = 16; off > 0; off >>= 1)
                c += __shfl_xor_sync(0xFFFFFFFFu, c, off);
            if (lane == 0) g_c = c + b2[0];
        }
    } else {
        if (t < BB) g_cnt[t] = 0;
        __syncthreads();
        for (int m = t; m < M_CNT; m += blockDim.x) {
            int b = bptr[m];
            int slot = atomicAdd(&g_cnt[b], 1);
            if (slot < BATCH_CAP) g_list[b * BATCH_CAP + slot] = m;
        }
    }
}

__device__ __forceinline__ float warp_reduce_sum(float v) {
    #pragma unroll
    for (int off = 16; off > 0; off >>= 1)
        v += __shfl_xor_sync(0xFFFFFFFFu, v, off);
    return v;
}

// ---------------------------------------------------------------------------
// Lemma phase: 8 lanes per edge, 4 edges per warp. Per-lane register
// accumulation over 8 chunks of D; one 3-shfl reduction serves all 4 edges.
// Next quad's indices are prefetched to hide the index->gather serial chain.
// ---------------------------------------------------------------------------
__device__ __forceinline__ void lemma_phase(
    const float* __restrict__ tok, const int* __restrict__ eidx,
    const float* __restrict__ s_v, float* __restrict__ out, int block)
{
    const int lane = threadIdx.x & 31;
    const int sub  = lane >> 3;          // which edge of the quad (0..3)
    const int kl   = lane & 7;           // lane within edge (0..7)
    const int warp   = (block * blockDim.x + threadIdx.x) >> 5;
    const int nwarps = (LEMMA_BLOCKS * blockDim.x) >> 5;

    const float4* vv = reinterpret_cast<const float4*>(s_v);
    const float4* tk = reinterpret_cast<const float4*>(tok);
    const float c = g_c;

    int q = warp;
    if (q >= N_QUADS) return;

    // Prime the pipeline: load this quad's indices.
    int e    = q * 4 + sub;
    int sidx = eidx[e];
    int gidx = eidx[E_EDGES + e];

    while (true) {
        const int qn = q + nwarps;
        // Prefetch next quad's indices (independent of current compute).
        int sidx_n = 0, gidx_n = 0, en = 0;
        const bool more = (qn < N_QUADS);
        if (more) {
            en     = qn * 4 + sub;
            sidx_n = eidx[en];
            gidx_n = eidx[E_EDGES + en];
        }

        const float4* rs = tk + (size_t)sidx * (ROW_STRIDE / 4);
        const float4* rg = tk + (size_t)gidx * (ROW_STRIDE / 4);

        float acc = 0.f;
        #pragma unroll 4
        for (int ch = 0; ch < 8; ch++) {
            const float4 sv = rs[ch * 8 + kl];
            const float4 gv = rg[ch * 8 + kl];
            const float4 w  = vv[ch * 8 + kl];
            acc = fmaf(sv.x * gv.x, w.x, acc);
            acc = fmaf(sv.y * gv.y, w.y, acc);
            acc = fmaf(sv.z * gv.z, w.z, acc);
            acc = fmaf(sv.w * gv.w, w.w, acc);
        }

        // Reduce within each 8-lane group (serves all 4 edges at once).
        acc += __shfl_xor_sync(0xFFFFFFFFu, acc, 4);
        acc += __shfl_xor_sync(0xFFFFFFFFu, acc, 2);
        acc += __shfl_xor_sync(0xFFFFFFFFu, acc, 1);
        if (kl == 0) out[e] = acc + c;   // 4 lanes store 16 contiguous bytes

        if (!more) break;
        q = qn; e = en; sidx = sidx_n; gidx = gidx_n;
    }
}

// ---------------------------------------------------------------------------
// lm phase: block per (batch, s-tile of 32); loop over the batch's m's.
// The 32KB candidate tile is L1-resident after the first m.
// ---------------------------------------------------------------------------
__device__ __forceinline__ void lm_phase(
    const float* __restrict__ tok, const int* __restrict__ lm_idx,
    const int* __restrict__ tpm, float* __restrict__ out,
    float* __restrict__ q, int blk)
{
    const int b    = blk / N_TILES;
    const int tile = blk % N_TILES;
    const int s0   = tile * S_TILE;

    const int t    = threadIdx.x;
    const int lane = t & 31;
    const int warp = t >> 5;             // 0..7

    const int cnt = min(g_cnt[b], BATCH_CAP);
    const int* list = g_list + b * BATCH_CAP;

    const float* base = tok + ((size_t)b * SS + s0) * ROW_STRIDE;
    const int* mrow = tpm + (size_t)b * SS + s0;

    for (int it = 0; it < cnt; it++) {
        const int m = list[it];
        __syncthreads();
        q[t] = tok[(size_t)lm_idx[m] * DD + t];
        __syncthreads();

        const float4* qv = reinterpret_cast<const float4*>(q);
        const float4 q0 = qv[lane];
        const float4 q1 = qv[32 + lane];

        float* orow = out + (size_t)E_EDGES + (size_t)m * SS + s0;

        #pragma unroll
        for (int si = warp; si < S_TILE; si += 8) {
            const float4* cr = reinterpret_cast<const float4*>(base + (size_t)si * ROW_STRIDE);
            const float4 c0 = cr[lane];
            const float4 c1 = cr[32 + lane];

            float acc = 0.f;
            acc = fmaf(q0.x, c0.x, acc);
            acc = fmaf(q0.y, c0.y, acc);
            acc = fmaf(q0.z, c0.z, acc);
            acc = fmaf(q0.w, c0.w, acc);
            acc = fmaf(q1.x, c1.x, acc);
            acc = fmaf(q1.y, c1.y, acc);
            acc = fmaf(q1.z, c1.z, acc);
            acc = fmaf(q1.w, c1.w, acc);

            acc = warp_reduce_sum(acc);
            if (lane == 0)
                orow[si] = (mrow[si] != 0) ? acc : NEG_INF_F;
        }
    }
}

// ---------------------------------------------------------------------------
__global__ __launch_bounds__(256)
void fused_kernel(const float* __restrict__ tok,
                  const int*   __restrict__ eidx,
                  const int*   __restrict__ lm_idx,
                  const int*   __restrict__ tpm,
                  float*       __restrict__ out)
{
    __shared__ float s_buf[DD];          // lemma: v staging; lm: query row
    const int blk = blockIdx.x;
    if (blk < LEMMA_BLOCKS) {
        s_buf[threadIdx.x] = g_v[threadIdx.x];
        __syncthreads();
        lemma_phase(tok, eidx, s_buf, out, blk);
    } else {
        lm_phase(tok, lm_idx, tpm, out, s_buf, blk - LEMMA_BLOCKS);
    }
}

// ---------------------------------------------------------------------------
// Inputs (metadata order):
//  0 token_reprs f32 [B,S,T,D]
//  1 w1 f32 [D,D/2]  2 b1 f32 [D/2]  3 w2 f32 [D/2,1]  4 b2 f32 [1]
//  5 edge_index i32 [2,E]  6 lm_indices i32 [M]  7 batch_pointers i32 [M]
//  8 tree_padding_mask (bool -> int32) [B,S]
// Output: float32, E lemmas followed by M*S lm_preds.
// ---------------------------------------------------------------------------
extern "C" void kernel_launch(void* const* d_in, const int* in_sizes, int n_in,
                              void* d_out, int out_size) {
    const float* tok  = (const float*)d_in[0];
    const float* w1   = (const float*)d_in[1];
    const float* b1   = (const float*)d_in[2];
    const float* w2   = (const float*)d_in[3];
    const float* b2   = (const float*)d_in[4];
    const int*   eidx = (const int*)d_in[5];
    const int*   lmi  = (const int*)d_in[6];
    const int*   bpt  = (const int*)d_in[7];
    const int*   tpm  = (const int*)d_in[8];
    float* out = (float*)d_out;

    prep_kernel<<<9, 256>>>(w1, b1, w2, b2, bpt);
    fused_kernel<<<TOTAL_BLOCKS, 256>>>(tok, eidx, lmi, tpm, out);
}